// round 13
// baseline (speedup 1.0000x reference)
#include <cuda_runtime.h>

// Problem constants
#define BATCH   4
#define NPTS    16384
#define HALF    8192
#define FDIM    32
#define GD      16               // cells per axis (in CDF/u-space)
#define NC      (GD*GD*GD)       // 4096 cells per batch

typedef unsigned int u32;

// Output layout (concatenated tuple, float32)
#define OFF_VPC   0
#define OFF_VFEAT (BATCH * HALF * 3)                  // 98304
#define OFF_NIDX  (OFF_VFEAT + BATCH * HALF * FDIM)   // 1146880
#define OFF_RNDS  (OFF_NIDX + BATCH * HALF)           // 1179648

// Cell boundaries in x-space: standard normal quantiles Phi^-1(i/16).
__constant__ float c_bnd[GD + 1] = {
    -1e30f,
    -1.5341206f, -1.1503494f, -0.8871466f, -0.6744898f,
    -0.4887764f, -0.3186394f, -0.1573107f,  0.0f,
     0.1573107f,  0.3186394f,  0.4887764f,  0.6744898f,
     0.8871466f,  1.1503494f,  1.5341206f,
     1e30f
};

// ---------------------------------------------------------------------------
// Scratch (device globals; no allocation allowed). Zero-initialized at module
// load; g_cnt is re-zeroed by knn_kernel's tail each run (graph replays).
// ---------------------------------------------------------------------------
__device__ float4 g_valid[BATCH][HALF];
__device__ float4 g_query[BATCH][HALF];
__device__ int    g_pcell[BATCH][HALF];
__device__ int    g_qcell[BATCH][HALF];
__device__ int    g_cnt[2][BATCH][NC];
__device__ int    g_off[2][BATCH][NC+1];
__device__ int    g_cur[2][BATCH][NC];
__device__ float4 g_spt[BATCH][HALF];     // cell-sorted points (2x,2y,2z,p2)
__device__ int    g_sid[BATCH][HALF];     // original point index
__device__ float4 g_sq[BATCH][HALF];      // cell-sorted queries (x,y,z,q2)
__device__ int    g_sqid[BATCH][HALF];
__device__ int    g_sqc[BATCH][HALF];

// ||v||^2 left-to-right, no FMA contraction (match jax fp32 semantics)
__device__ __forceinline__ float sq3(float x, float y, float z) {
    return __fadd_rn(__fadd_rn(__fmul_rn(x, x), __fmul_rn(y, y)), __fmul_rn(z, z));
}

__device__ __forceinline__ int axis_cell(float x) {
    float u = __fmaf_rn(erff(x * 0.70710678f), 0.5f, 0.5f);
    int c = (int)(u * (float)GD);
    return max(0, min(GD - 1, c));
}
__device__ __forceinline__ int cell_of(float x, float y, float z) {
    return (axis_cell(z) * GD + axis_cell(y)) * GD + axis_cell(x);
}

// Order-preserving float->u32 encode (monotone incl. +inf)
__device__ __forceinline__ u32 fenc32(float f) {
    u32 u = __float_as_uint(f);
    return u ^ ((u32)((int)u >> 31) | 0x80000000u);
}
__device__ __forceinline__ float fdec32(u32 e) {
    u32 u = (e & 0x80000000u) ? (e ^ 0x80000000u) : ~e;
    return __uint_as_float(u);
}

__device__ __forceinline__ bool lt2(float d, int i, float e, int j) {
    return d < e || (d == e && i < j);
}

// Insert candidate (d, i) into sorted top-2 state, deduping by id.
__device__ __forceinline__ void ins2(float d, int i,
                                     float& bd1, int& bi1,
                                     float& bd2, int& bi2) {
    if (i == bi1 || i == bi2) return;
    if (lt2(d, i, bd1, bi1)) {
        bd2 = bd1; bi2 = bi1; bd1 = d; bi1 = i;
    } else if (lt2(d, i, bd2, bi2)) {
        bd2 = d; bi2 = i;
    }
}

// Exact final top-2 reduce (once per query)
__device__ __forceinline__ void warp_reduce_top2(float& bd1, int& bi1,
                                                 float& bd2, int& bi2) {
#pragma unroll
    for (int o = 16; o > 0; o >>= 1) {
        float e1 = __shfl_xor_sync(0xFFFFFFFFu, bd1, o);
        float e2 = __shfl_xor_sync(0xFFFFFFFFu, bd2, o);
        int j1 = __shfl_xor_sync(0xFFFFFFFFu, bi1, o);
        int j2 = __shfl_xor_sync(0xFFFFFFFFu, bi2, o);
        ins2(e1, j1, bd1, bi1, bd2, bi2);
        ins2(e2, j2, bd1, bi1, bd2, bi2);
    }
}

// Cheap conservative UPPER bound on global bd2 via 2x hardware REDUX.
// m2 >= true global 2nd-smallest distance (equal-distance collisions only
// raise it) => safe for termination tests.
__device__ __forceinline__ float warp_ub2(float bd1, float bd2) {
    u32 e1 = fenc32(bd1);
    u32 m1 = __reduce_min_sync(0xFFFFFFFFu, e1);
    u32 c = (e1 == m1) ? fenc32(bd2) : e1;
    u32 m2 = __reduce_min_sync(0xFFFFFFFFu, c);
    return fdec32(m2);
}

__device__ __forceinline__ float score(float qx, float qy, float qz, float q2,
                                       float4 P) {
    float dot2 = __fadd_rn(__fadd_rn(__fmul_rn(qx, P.x), __fmul_rn(qy, P.y)),
                           __fmul_rn(qz, P.z));
    return __fsub_rn(__fadd_rn(q2, P.w), dot2);
}

// ---------------------------------------------------------------------------
// K1 (launch 0): gathers + binning + histogram
// ---------------------------------------------------------------------------
__global__ void gather_kernel(const float* __restrict__ pc,
                              const float4* __restrict__ feats4,
                              const int* __restrict__ rnds,
                              float* __restrict__ out) {
    int i = blockIdx.x * blockDim.x + threadIdx.x;
    const int WF = BATCH * HALF * 8;
    const int WP = BATCH * HALF;

    if (i < WF) {
        int c = i & 7;
        int t = (i >> 3) & (HALF - 1);
        int b = i >> 16;
        int v = rnds[t];
        float4 val = feats4[(b * NPTS + v) * 8 + c];
        ((float4*)(out + OFF_VFEAT))[(b * HALF + t) * 8 + c] = val;
        return;
    }
    i -= WF;
    if (i < WP) {
        int t = i & (HALF - 1);
        int b = i >> 13;
        int v = rnds[t];
        int base = (b * NPTS + v) * 3;
        float x = pc[base + 0], y = pc[base + 1], z = pc[base + 2];
        int ob = OFF_VPC + (b * HALF + t) * 3;
        out[ob + 0] = x; out[ob + 1] = y; out[ob + 2] = z;
        g_valid[b][t] = make_float4(2.0f * x, 2.0f * y, 2.0f * z, sq3(x, y, z));
        int cid = cell_of(x, y, z);
        g_pcell[b][t] = cid;
        atomicAdd(&g_cnt[0][b][cid], 1);
        return;
    }
    i -= WP;
    if (i < WP) {
        int t = i & (HALF - 1);
        int b = i >> 13;
        int v = rnds[HALF + t];
        int base = (b * NPTS + v) * 3;
        float x = pc[base + 0], y = pc[base + 1], z = pc[base + 2];
        g_query[b][t] = make_float4(x, y, z, sq3(x, y, z));
        int cid = cell_of(x, y, z);
        g_qcell[b][t] = cid;
        atomicAdd(&g_cnt[1][b][cid], 1);
        return;
    }
    i -= WP;
    if (i < NPTS) out[OFF_RNDS + i] = (float)rnds[i];
}

// ---------------------------------------------------------------------------
// K2 (launch 1): exclusive scan via two-level warp shuffle scan
// ---------------------------------------------------------------------------
__global__ void __launch_bounds__(1024) scan_kernel() {
    int kind = blockIdx.x >> 2;
    int b = blockIdx.x & 3;
    const int CPT = NC / 1024;  // 4
    int tid = threadIdx.x;
    int lane = tid & 31;
    int wid = tid >> 5;

    int loc[CPT];
    int s = 0;
    const int* cnt = g_cnt[kind][b];
#pragma unroll
    for (int j = 0; j < CPT; ++j) { loc[j] = s; s += cnt[tid * CPT + j]; }

    int inc = s;
#pragma unroll
    for (int o = 1; o < 32; o <<= 1) {
        int v = __shfl_up_sync(0xFFFFFFFFu, inc, o);
        if (lane >= o) inc += v;
    }
    __shared__ int wsum[32];
    if (lane == 31) wsum[wid] = inc;
    __syncthreads();
    if (wid == 0) {
        int v = wsum[lane];
        int wi = v;
#pragma unroll
        for (int o = 1; o < 32; o <<= 1) {
            int u = __shfl_up_sync(0xFFFFFFFFu, wi, o);
            if (lane >= o) wi += u;
        }
        wsum[lane] = wi - v;
    }
    __syncthreads();
    int base = wsum[wid] + (inc - s);

    int* off_arr = g_off[kind][b];
    int* cur_arr = g_cur[kind][b];
#pragma unroll
    for (int j = 0; j < CPT; ++j) {
        int v = base + loc[j];
        off_arr[tid * CPT + j] = v;
        cur_arr[tid * CPT + j] = v;
    }
    if (tid == 1023) off_arr[NC] = base + s;
}

// ---------------------------------------------------------------------------
// K3 (launch 2): scatter into cell-sorted order
// ---------------------------------------------------------------------------
__global__ void scatter_kernel() {
    int i = blockIdx.x * blockDim.x + threadIdx.x;
    if (i >= 2 * BATCH * HALF) return;
    int kind = i >> 15;
    int b = (i >> 13) & (BATCH - 1);
    int t = i & (HALF - 1);
    if (kind == 0) {
        int cid = g_pcell[b][t];
        int pos = atomicAdd(&g_cur[0][b][cid], 1);
        g_spt[b][pos] = g_valid[b][t];
        g_sid[b][pos] = t;
    } else {
        int cid = g_qcell[b][t];
        int pos = atomicAdd(&g_cur[1][b][cid], 1);
        g_sq[b][pos] = g_query[b][t];
        g_sqid[b][pos] = t;
        g_sqc[b][pos] = cid;
    }
}

// ---------------------------------------------------------------------------
// K4 (launch 3 — ncu slot): warp-per-query KNN, coordination-diet version.
// - NO intermediate full reduces: per-lane top-2 accumulates across phases;
//   termination uses a 2xREDUX conservative upper bound on global bd2.
// - 2-way unrolled candidate loop: two independent binary searches + loads
//   in flight (overlapped shfl chains).
// - Exact pair-butterfly reduce ONCE at the end; id-dedup keeps interior
//   rescans harmless. Scoring formula exact => bit-identical to reference.
// ---------------------------------------------------------------------------
template <int R>
__device__ __forceinline__ void scan_box(int qcx, int qcy, int qcz,
                                         float qx, float qy, float qz, float q2,
                                         const float4* __restrict__ pts,
                                         const int* __restrict__ ids,
                                         const int* __restrict__ offs,
                                         int lane,
                                         float& bd1, int& bi1,
                                         float& bd2, int& bi2) {
    const int NR = (2 * R + 1) * (2 * R + 1);
    int p0 = 0, len = 0;
    if (lane < NR) {
        int dy = lane % (2 * R + 1) - R;
        int dz = lane / (2 * R + 1) - R;
        int cy = qcy + dy, cz = qcz + dz;
        if (cy >= 0 && cy < GD && cz >= 0 && cz < GD) {
            int cx0 = max(qcx - R, 0), cx1 = min(qcx + R, GD - 1);
            int rowbase = (cz * GD + cy) * GD;
            p0 = __ldg(&offs[rowbase + cx0]);
            len = __ldg(&offs[rowbase + cx1 + 1]) - p0;
        }
    }
    // warp inclusive scan of len
    int inc = len;
#pragma unroll
    for (int o = 1; o < 32; o <<= 1) {
        int v = __shfl_up_sync(0xFFFFFFFFu, inc, o);
        if (lane >= o) inc += v;
    }
    int excl = inc - len;
    int T = __shfl_sync(0xFFFFFFFFu, inc, NR - 1);

    // 2-way unrolled: two independent searches/loads per iteration
    for (int base = 0; base < T; base += 64) {
        int c0 = base + lane;
        int c1 = base + 32 + lane;
        bool a0 = c0 < T, a1 = c1 < T;
        int cc0 = a0 ? c0 : (T - 1);
        int cc1 = a1 ? c1 : (T - 1);
        int lo0 = 0, lo1 = 0;
#pragma unroll
        for (int step = 16; step > 0; step >>= 1) {
            int m0 = lo0 + step, m1 = lo1 + step;
            int v0 = __shfl_sync(0xFFFFFFFFu, excl, min(m0, 31));
            int v1 = __shfl_sync(0xFFFFFFFFu, excl, min(m1, 31));
            if (m0 < NR && v0 <= cc0) lo0 = m0;
            if (m1 < NR && v1 <= cc1) lo1 = m1;
        }
        int pA = __shfl_sync(0xFFFFFFFFu, p0, lo0) +
                 (cc0 - __shfl_sync(0xFFFFFFFFu, excl, lo0));
        int pB = __shfl_sync(0xFFFFFFFFu, p0, lo1) +
                 (cc1 - __shfl_sync(0xFFFFFFFFu, excl, lo1));
        float4 P0 = pts[pA];
        float4 P1 = pts[pB];
        if (a0) {
            float d2 = score(qx, qy, qz, q2, P0);
            if (d2 <= bd2) ins2(d2, ids[pA], bd1, bi1, bd2, bi2);
        }
        if (a1) {
            float d2 = score(qx, qy, qz, q2, P1);
            if (d2 <= bd2) ins2(d2, ids[pB], bd1, bi1, bd2, bi2);
        }
    }
}

// warp-uniform termination using conservative bd2 upper bound
__device__ __forceinline__ bool term_ok(int qcx, int qcy, int qcz, int r,
                                        float qx, float qy, float qz,
                                        float ub2) {
    const float INF = __int_as_float(0x7f800000);
    if (!(ub2 < INF)) return false;
    float lb = INF;
    if (qcx - r > 0)      lb = fminf(lb, qx - c_bnd[qcx - r]);
    if (qcx + r < GD - 1) lb = fminf(lb, c_bnd[qcx + r + 1] - qx);
    if (qcy - r > 0)      lb = fminf(lb, qy - c_bnd[qcy - r]);
    if (qcy + r < GD - 1) lb = fminf(lb, c_bnd[qcy + r + 1] - qy);
    if (qcz - r > 0)      lb = fminf(lb, qz - c_bnd[qcz - r]);
    if (qcz + r < GD - 1) lb = fminf(lb, c_bnd[qcz + r + 1] - qz);
    float lba = fmaxf(lb - 1e-5f, 0.0f);
    return lba * lba > ub2 * 1.001f + 1e-4f;
}

__global__ void __launch_bounds__(256) knn_kernel(float* __restrict__ out) {
    int w = (blockIdx.x * blockDim.x + threadIdx.x) >> 5;
    int lane = threadIdx.x & 31;
    int b = w >> 13;
    int s = w & (HALF - 1);

    float4 q = g_sq[b][s];
    int qi = g_sqid[b][s];
    int qc = g_sqc[b][s];
    const float qx = q.x, qy = q.y, qz = q.z, q2 = q.w;

    int qcx = qc & (GD - 1);
    int qcy = (qc >> 4) & (GD - 1);
    int qcz = qc >> 8;

    const float INF = __int_as_float(0x7f800000);
    float bd1 = INF, bd2 = INF;
    int bi1 = 0x7fffffff, bi2 = 0x7fffffff;

    const float4* __restrict__ pts = g_spt[b];
    const int* __restrict__ ids = g_sid[b];
    const int* __restrict__ offs = g_off[0][b];

    // Phase 1: 3x3x3 box (9 runs); no reduce, per-lane accumulation
    scan_box<1>(qcx, qcy, qcz, qx, qy, qz, q2, pts, ids, offs, lane,
                bd1, bi1, bd2, bi2);

    float ub2 = warp_ub2(bd1, bd2);
    if (!term_ok(qcx, qcy, qcz, 1, qx, qy, qz, ub2)) {
        // Phase 2: 5x5x5 box (25 runs; interior rescan deduped by id)
        scan_box<2>(qcx, qcy, qcz, qx, qy, qz, q2, pts, ids, offs, lane,
                    bd1, bi1, bd2, bi2);

        ub2 = warp_ub2(bd1, bd2);
        if (!term_ok(qcx, qcy, qcz, 2, qx, qy, qz, ub2)) {
            // Phase 3: bounded fallback — full warp-parallel brute force
            for (int p = lane; p < HALF; p += 32) {
                float d2 = score(qx, qy, qz, q2, pts[p]);
                if (d2 <= bd2) ins2(d2, ids[p], bd1, bi1, bd2, bi2);
            }
        }
    }

    // single exact reduce
    warp_reduce_top2(bd1, bi1, bd2, bi2);

    if (lane == 0) out[OFF_NIDX + (b << 13) + qi] = (float)bi2;

    // Tail: re-zero histograms for next graph replay (4096 blocks x 8 ints)
    if (threadIdx.x < 8) {
        ((int*)g_cnt)[blockIdx.x * 8 + threadIdx.x] = 0;
    }
}

// ---------------------------------------------------------------------------
extern "C" void kernel_launch(void* const* d_in, const int* in_sizes, int n_in,
                              void* d_out, int out_size) {
    const float*  pc    = (const float*)d_in[0];
    const float4* feats = (const float4*)d_in[1];
    const int*    rnds  = (const int*)d_in[2];
    float*        out   = (float*)d_out;
    (void)in_sizes; (void)n_in; (void)out_size;

    const int total = BATCH * HALF * 8 + 2 * BATCH * HALF + NPTS;  // 344064
    gather_kernel<<<total / 256, 256>>>(pc, feats, rnds, out);

    scan_kernel<<<2 * BATCH, 1024>>>();
    scatter_kernel<<<(2 * BATCH * HALF + 255) / 256, 256>>>();

    // one warp per query: 32768 warps = 4096 blocks of 256 threads
    knn_kernel<<<BATCH * HALF * 32 / 256, 256>>>(out);
}